// round 6
// baseline (speedup 1.0000x reference)
#include <cuda_runtime.h>
#include <cuda_bf16.h>
#include <cstdint>

// I=16, O=8, J=4, B=16 -> n_in=1024, n_out=256, K=81 projectors.
// Each output quad out[b, ij_r*4+ch, 4*gc..+3] is a masked sum of up to 4
// gathered input quads. In quad (float4) units, with u = global thread id
//   (u = ((b*64+ij_r)*4+ch)*64+gc, which is ALSO the linear output quad index)
// the common base address is a 4-shift bit-permutation of u:
//   base = ((u&7)<<1) + ((u&0xF8)<<2) + ((u&0x700)<<3) + ((u&0x3F800)<<4)
// and the four source quads sit at CONSTANT offsets from base:
//   B = base+0,  C = base+1025,  D = base+16400,  center = base+17425
// center always; C iff i_r==i_c (u bits 11-13 == 3-5... see below);
// D iff j_r==j_c; B iff both. 49/64 threads need ONLY the center load.

__device__ __forceinline__ void add2(unsigned long long& a, unsigned long long b)
{
    asm("add.rn.f32x2 %0, %0, %1;" : "+l"(a) : "l"(b));
}

__global__ __launch_bounds__(256, 8)
void pool2d_density_kernel(const float4* __restrict__ xq, float4* __restrict__ oq)
{
    const unsigned u = blockIdx.x * 256 + threadIdx.x;   // output quad index

    // 4-shift bit permutation -> base quad index into X
    const unsigned base = ((u & 7u)       << 1)
                        + ((u & 0xF8u)    << 2)
                        + ((u & 0x700u)   << 3)
                        + ((u & 0x3F800u) << 4);

    const ulonglong2* __restrict__ p = (const ulonglong2*)xq + base;

    // center term (always): one LDG.128, viewed as two f32x2 packs
    ulonglong2 acc = __ldg(p + 17425);

    // match predicates straight from bit fields of u
    const bool im = ((u >> 11) & 7u) == ((u >> 3) & 7u);   // i_r == i_c
    const bool jm = ((u >> 8)  & 7u) == (u & 7u);          // j_r == j_c

    if (im) {                       // C group
        ulonglong2 v = __ldg(p + 1025);
        add2(acc.x, v.x); add2(acc.y, v.y);
    }
    if (jm) {                       // D group
        ulonglong2 v = __ldg(p + 16400);
        add2(acc.x, v.x); add2(acc.y, v.y);
    }
    if (im && jm) {                 // B group
        ulonglong2 v = __ldg(p);
        add2(acc.x, v.x); add2(acc.y, v.y);
    }

    // store address == u: fully coalesced 128B stores per warp
    ((ulonglong2*)oq)[u] = acc;
}

extern "C" void kernel_launch(void* const* d_in, const int* in_sizes, int n_in,
                              void* d_out, int out_size)
{
    const float4* x = (const float4*)d_in[0];   // (16, 1024, 1024) fp32 as quads
    float4* out = (float4*)d_out;               // (16, 256, 256) fp32 as quads

    // 262144 output quads, 1 per thread: 1024 blocks x 256 threads
    pool2d_density_kernel<<<1024, 256>>>(x, out);
}

// round 7
// speedup vs baseline: 1.0048x; 1.0048x over previous
#include <cuda_runtime.h>
#include <cuda_bf16.h>
#include <cstdint>

// I=16, O=8, J=4, B=16 -> n_in=1024, n_out=256, K=81 projectors.
// Each output quad out[b, ij_r*4+ch, 4*gc..+3] is a sum of 1-4 gathered input
// quads. With u = global thread id (== linear output quad index), the common
// base address in quad units is a 4-shift bit-permutation of u:
//   base = ((u&7)<<1) + ((u&0xF8)<<2) + ((u&0x700)<<3) + ((u&0x3F800)<<4)
//   (fields: b<<18 | i_r<<15 | j_r<<11 | ch<<8 | i_c<<5 | j_c<<1)
// and the four source quads sit at CONSTANT offsets from base:
//   B = base+0   (iff i_r==i_c && j_r==j_c)
//   C = base+1025   (iff i_r==i_c)
//   D = base+16400  (iff j_r==j_c)
//   center = base+17425  (always)
// 49/64 threads need ONLY the center load. Predicates reduce to
// blockIdx-vs-threadIdx field compares (blockIdx side is warp-uniform).

__global__ __launch_bounds__(256, 8)
void pool2d_density_kernel(const float4* __restrict__ xq, float4* __restrict__ oq)
{
    const unsigned tid = threadIdx.x;
    const unsigned bid = blockIdx.x;
    const unsigned u   = bid * 256u + tid;             // output quad index

    // predicates: u bits 11-13 vs 3-5 (i match), bits 8-10 vs 0-2 (j match).
    // bits 8+ of u come from bid, bits 0-7 from tid.
    const bool im = ((bid >> 3) & 7u) == ((tid >> 3) & 7u);
    const bool jm = (bid & 7u) == (tid & 7u);

    // 4-shift bit permutation -> base quad index into X
    const unsigned base = ((u & 7u)       << 1)
                        + ((u & 0xF8u)    << 2)
                        + ((u & 0x700u)   << 3)
                        + ((u & 0x3F800u) << 4);

    const float4* __restrict__ p = xq + base;

    // center load first; conditional loads hoisted ahead of all arithmetic so
    // they overlap the center load's latency.
    float4 acc = __ldg(p + 17425);

    float4 vC, vD, vB;
    if (im)       vC = __ldg(p + 1025);
    if (jm)       vD = __ldg(p + 16400);
    if (im && jm) vB = __ldg(p);

    if (im) {
        acc.x += vC.x; acc.y += vC.y; acc.z += vC.z; acc.w += vC.w;
    }
    if (jm) {
        acc.x += vD.x; acc.y += vD.y; acc.z += vD.z; acc.w += vD.w;
    }
    if (im && jm) {
        acc.x += vB.x; acc.y += vB.y; acc.z += vB.z; acc.w += vB.w;
    }

    // store address == u: fully coalesced 128B stores per warp
    oq[u] = acc;
}

extern "C" void kernel_launch(void* const* d_in, const int* in_sizes, int n_in,
                              void* d_out, int out_size)
{
    const float4* x = (const float4*)d_in[0];   // (16, 1024, 1024) fp32 as quads
    float4* out = (float4*)d_out;               // (16, 256, 256) fp32 as quads

    // 262144 output quads, 1 per thread: 1024 blocks x 256 threads
    // (~7 blocks/SM, single wave).
    pool2d_density_kernel<<<1024, 256>>>(x, out);
}